// round 11
// baseline (speedup 1.0000x reference)
#include <cuda_runtime.h>
#include <cuda_bf16.h>
#include <math.h>
#include <stdint.h>

// Problem constants
#define N_ROWS   512
#define N_CAMS   8
#define M_PER    2048
#define D_FULL   4096
#define K_HALF   2048
#define P_TOT    16384
#define TOPK     54
#define INV_BETA 20.0f
#define CAND_CAP 4096

// ---------------- scratch (device globals) ------------------------------------
__device__ float g_sims[2ull * N_ROWS * P_TOT];                 // 64 MB
__device__ float g_loss[2 * N_ROWS * 3];
__device__ __nv_bfloat16 g_featB[(size_t)N_ROWS * D_FULL];      // 4 MB
__device__ __nv_bfloat16 g_memB[(size_t)P_TOT * D_FULL];        // 128 MB

// ---------------- helpers ------------------------------------------------------
__device__ __forceinline__ uint32_t smem_u32(const void* p) {
    uint32_t a;
    asm("{ .reg .u64 t; cvta.to.shared.u64 t, %1; cvt.u32.u64 %0, t; }"
        : "=r"(a) : "l"(p));
    return a;
}
__device__ __forceinline__ void cp16(uint32_t s, const void* g) {
    asm volatile("cp.async.cg.shared.global [%0], [%1], 16;" :: "r"(s), "l"(g));
}
#define CP_COMMIT() asm volatile("cp.async.commit_group;" ::: "memory")

__device__ __forceinline__ void mma16(float* d, const uint32_t* a,
                                      uint32_t b0, uint32_t b1) {
    asm volatile(
        "mma.sync.aligned.m16n8k16.row.col.f32.bf16.bf16.f32 "
        "{%0,%1,%2,%3}, {%4,%5,%6,%7}, {%8,%9}, {%0,%1,%2,%3};"
        : "+f"(d[0]), "+f"(d[1]), "+f"(d[2]), "+f"(d[3])
        : "r"(a[0]), "r"(a[1]), "r"(a[2]), "r"(a[3]), "r"(b0), "r"(b1));
}
__device__ __forceinline__ void ldsm4(uint32_t& r0, uint32_t& r1,
                                      uint32_t& r2, uint32_t& r3, uint32_t addr) {
    asm volatile("ldmatrix.sync.aligned.m8n8.x4.shared.b16 {%0,%1,%2,%3}, [%4];"
                 : "=r"(r0), "=r"(r1), "=r"(r2), "=r"(r3) : "r"(addr));
}

// ---------------- fp32 -> bf16 conversion --------------------------------------
__global__ void convA_k(const float* __restrict__ f) {
    size_t i = (size_t)blockIdx.x * 256 + threadIdx.x;
    float4 v = ((const float4*)f)[i];
    __nv_bfloat162 p0 = __floats2bfloat162_rn(v.x, v.y);
    __nv_bfloat162 p1 = __floats2bfloat162_rn(v.z, v.w);
    uint2 o; o.x = *(uint32_t*)&p0; o.y = *(uint32_t*)&p1;
    ((uint2*)g_featB)[i] = o;
}
__global__ void convB_k(const float* __restrict__ m) {
    size_t i = (size_t)blockIdx.x * 256 + threadIdx.x;
    float4 v = ((const float4*)m)[i];
    __nv_bfloat162 p0 = __floats2bfloat162_rn(v.x, v.y);
    __nv_bfloat162 p1 = __floats2bfloat162_rn(v.z, v.w);
    uint2 o; o.x = *(uint32_t*)&p0; o.y = *(uint32_t*)&p1;
    ((uint2*)g_memB)[i] = o;
}

// ---------------- bf16 mma.sync GEMM: 128x128 tile, GBK=64, 3-stage, swizzle ---
#define GBK      64
#define NSTG     (K_HALF / GBK)     // 32
#define STG_B    32768u
#define B_OFF    16384u

__device__ __forceinline__ void load_stage(int st, int tid, int mtile, int ntile,
                                           int h, uint32_t sbase) {
    const uint32_t buf = sbase + (uint32_t)(st % 3) * STG_B;
    const int kg = h * K_HALF + st * GBK;
#pragma unroll
    for (int i = 0; i < 4; i++) {
        int idx = tid + i * 256;
        int r = idx >> 3, ch = idx & 7;
        cp16(buf + (uint32_t)r * 128 + (uint32_t)((ch ^ (r & 7)) << 4),
             g_featB + (size_t)(mtile * 128 + r) * D_FULL + kg + ch * 8);
    }
#pragma unroll
    for (int i = 0; i < 4; i++) {
        int idx = tid + i * 256;
        int r = idx >> 3, ch = idx & 7;
        cp16(buf + B_OFF + (uint32_t)r * 128 + (uint32_t)((ch ^ (r & 7)) << 4),
             g_memB + (size_t)(ntile * 128 + r) * D_FULL + kg + ch * 8);
    }
    CP_COMMIT();
}

__global__ void __launch_bounds__(256, 2)
gemm_mma(void) {
    extern __shared__ char sm[];
    const uint32_t sbase = smem_u32(sm);

    const int tid = threadIdx.x;
    const int bx = blockIdx.x;
    const int h  = blockIdx.y;
    const int ntile = bx >> 2;
    const int mtile = bx & 3;

    const int w  = tid >> 5;
    const int l  = tid & 31;
    const int wm = (w & 3) * 32;
    const int wn = (w >> 2) * 64;
    const int g  = l >> 2;
    const int tg = l & 3;

    const int rowA  = wm + (l & 15);
    const int hiA   = (l >> 4) & 1;
    const uint32_t aRow = (uint32_t)rowA * 128;
    const int swA = rowA & 7;

    const int rowB  = wn + (l & 7) + ((l >> 4) & 1) * 8;
    const int hiB   = (l >> 3) & 1;
    const uint32_t bRow = B_OFF + (uint32_t)rowB * 128;
    const int swB = rowB & 7;

    float acc[2][8][4];
#pragma unroll
    for (int mi = 0; mi < 2; mi++)
#pragma unroll
        for (int ni = 0; ni < 8; ni++)
#pragma unroll
            for (int c = 0; c < 4; c++) acc[mi][ni][c] = 0.0f;

    load_stage(0, tid, mtile, ntile, h, sbase);
    load_stage(1, tid, mtile, ntile, h, sbase);

    for (int st = 0; st < NSTG; st++) {
        if (st < NSTG - 1) asm volatile("cp.async.wait_group 1;" ::: "memory");
        else               asm volatile("cp.async.wait_group 0;" ::: "memory");
        __syncthreads();

        if (st + 2 < NSTG) load_stage(st + 2, tid, mtile, ntile, h, sbase);

        const uint32_t stg = sbase + (uint32_t)(st % 3) * STG_B;

#pragma unroll
        for (int ks = 0; ks < 4; ks++) {
            const int ccA = ks * 2 + hiA;
            const int ccB = ks * 2 + hiB;
            uint32_t a[2][4];
            ldsm4(a[0][0], a[0][1], a[0][2], a[0][3],
                  stg + aRow + (uint32_t)((ccA ^ swA) << 4));
            ldsm4(a[1][0], a[1][1], a[1][2], a[1][3],
                  stg + aRow + 16u * 128u + (uint32_t)((ccA ^ swA) << 4));
            uint32_t bb[4][4];
#pragma unroll
            for (int np = 0; np < 4; np++)
                ldsm4(bb[np][0], bb[np][1], bb[np][2], bb[np][3],
                      stg + bRow + (uint32_t)np * 16u * 128u +
                      (uint32_t)((ccB ^ swB) << 4));
#pragma unroll
            for (int ni = 0; ni < 8; ni++) {
                const uint32_t b0 = bb[ni >> 1][(ni & 1) * 2];
                const uint32_t b1 = bb[ni >> 1][(ni & 1) * 2 + 1];
                mma16(acc[0][ni], a[0], b0, b1);
                mma16(acc[1][ni], a[1], b0, b1);
            }
        }
    }

    const int colbase = ntile * 128 + wn;
#pragma unroll
    for (int mi = 0; mi < 2; mi++) {
        const int row = mtile * 128 + wm + mi * 16 + g;
        float* d0 = g_sims + ((size_t)(h * N_ROWS + row)) * P_TOT + colbase + tg * 2;
        float* d1 = d0 + (size_t)8 * P_TOT;
#pragma unroll
        for (int ni = 0; ni < 8; ni++) {
            *(float2*)(d0 + ni * 8) = make_float2(acc[mi][ni][0], acc[mi][ni][1]);
            *(float2*)(d1 + ni * 8) = make_float2(acc[mi][ni][2], acc[mi][ni][3]);
        }
    }
}

// ---------------- per-row loss reduction (2 gmem passes, plain gather) ------------
__device__ __forceinline__ uint32_t fkey(float v) {
    uint32_t u = __float_as_uint(v);
    return u ^ (uint32_t)(((int32_t)u >> 31) | 0x80000000);
}
__device__ __forceinline__ bool beats(float va, int ia, float vb, int ib) {
    return (va > vb) || (va == vb && ia < ib);
}

__global__ void __launch_bounds__(512, 3)
reduce_kernel(const int* __restrict__ cams, const int* __restrict__ proxy)
{
    __shared__ int   hist1[256];
    __shared__ int   hist2[256];
    __shared__ float wmax[16];
    __shared__ int   widx[16];
    __shared__ float red[16];
    __shared__ float candv[CAND_CAP];
    __shared__ int   candi[CAND_CAP];
    __shared__ float cv2[512];
    __shared__ int   ci2[512];
    __shared__ float camMax[N_CAMS];
    __shared__ int   camIdx[N_CAMS];
    __shared__ float s_ce, s_rp, s_top1;
    __shared__ int   s_b1, s_above, s_cnt, s_cnt2;
    __shared__ uint32_t s_thr;

    const int n = blockIdx.x;
    const int h = blockIdx.y;
    const int tid = threadIdx.x;
    const int w = tid >> 5, l = tid & 31;

    if (tid < 256) { hist1[tid] = 0; hist2[tid] = 0; }
    if (tid == 0) { s_cnt = 0; s_cnt2 = 0; }
    __syncthreads();

    const int c = cams[n];
    const int p = proxy[n];
    const float* rowg = g_sims + ((size_t)h * N_ROWS + n) * P_TOT;
    const float4* src4 = (const float4*)rowg;

    // ---- pass 1: per-cam argmax + 8-bit histogram (warp-aggregated) ----
    const int f4base = (w >> 1) * 512 + (w & 1) * 256;
    float bv = -3.0e38f; int bi = f4base * 4;
#pragma unroll
    for (int s = 0; s < 8; s++) {
        const int f4 = f4base + s * 32 + l;
        float4 v = __ldg(&src4[f4]);
        const int j = f4 * 4;
        if (v.x > bv) { bv = v.x; bi = j; }
        if (v.y > bv) { bv = v.y; bi = j + 1; }
        if (v.z > bv) { bv = v.z; bi = j + 2; }
        if (v.w > bv) { bv = v.w; bi = j + 3; }
        float comp[4] = {v.x, v.y, v.z, v.w};
#pragma unroll
        for (int q = 0; q < 4; q++) {
            uint32_t b = fkey(comp[q]) >> 24;
            unsigned m = __match_any_sync(0xffffffffu, b);
            if ((m & ((1u << l) - 1u)) == 0) atomicAdd(&hist1[b], __popc(m));
        }
    }
#pragma unroll
    for (int o = 16; o > 0; o >>= 1) {
        float ov = __shfl_down_sync(0xffffffffu, bv, o);
        int   oi = __shfl_down_sync(0xffffffffu, bi, o);
        if (ov > bv || (ov == bv && oi < bi)) { bv = ov; bi = oi; }
    }
    if (l == 0) { wmax[w] = bv; widx[w] = bi; }
    __syncthreads();

    if (tid < N_CAMS) {
        float a = wmax[2 * tid]; int ai = widx[2 * tid];
        float b2 = wmax[2 * tid + 1]; int bi2 = widx[2 * tid + 1];
        if (b2 > a || (b2 == a && bi2 < ai)) { a = b2; ai = bi2; }
        camMax[tid] = a; camIdx[tid] = ai;
    }
    if (tid == 32) {
        int cum = 0, b = 255;
        for (; b >= 0; b--) { cum += hist1[b]; if (cum >= TOPK) break; }
        s_b1 = b; s_above = cum - hist1[b];
    }
    __syncthreads();

    // ---- pass 2: CE sum-exp + plain predicated coarse gather ----
    const uint32_t b1 = (uint32_t)s_b1;
    const uint32_t cthr = b1 << 24;
    const float bm = camMax[c];
    float ssum = 0.0f;
#pragma unroll
    for (int s = 0; s < 8; s++) {
        const int f4 = tid + s * 512;
        float4 v = __ldg(&src4[f4]);
        if (s == c) {
            ssum += expf((v.x - bm) * INV_BETA) + expf((v.y - bm) * INV_BETA)
                  + expf((v.z - bm) * INV_BETA) + expf((v.w - bm) * INV_BETA);
        }
        float comp[4] = {v.x, v.y, v.z, v.w};
#pragma unroll
        for (int q = 0; q < 4; q++) {
            if (fkey(comp[q]) >= cthr) {
                int k = atomicAdd(&s_cnt, 1);
                if (k < CAND_CAP) { candv[k] = comp[q]; candi[k] = f4 * 4 + q; }
            }
        }
    }
#pragma unroll
    for (int o = 16; o > 0; o >>= 1) ssum += __shfl_down_sync(0xffffffffu, ssum, o);
    if (l == 0) red[w] = ssum;
    __syncthreads();

    // ---- hist2 over gathered candidates only ----
    const int nc1 = (s_cnt < CAND_CAP) ? s_cnt : CAND_CAP;
    for (int j = tid; j < nc1; j += 512) {
        const uint32_t k = fkey(candv[j]);
        if ((k >> 24) == b1) atomicAdd(&hist2[(k >> 16) & 0xFF], 1);
    }
    __syncthreads();

    if (tid == 0) {
        int cum = s_above, b = 255;
        for (; b >= 0; b--) { cum += hist2[b]; if (cum >= TOPK) break; }
        s_thr = (b1 << 24) | ((uint32_t)b << 16);
        float tot = 0.0f;
        for (int i = 0; i < 16; i++) tot += red[i];
        const float rp = __ldg(&rowg[p]);
        s_rp = rp;
        s_ce = bm * INV_BETA + logf(tot) - rp * INV_BETA;
    }
    __syncthreads();

    // ---- compact coarse -> fine (fkey >= thr), smem only ----
    const uint32_t thr = s_thr;
    for (int j = tid; j < nc1; j += 512) {
        const float v = candv[j];
        if (fkey(v) >= thr) {
            int k = atomicAdd(&s_cnt2, 1);
            if (k < 512) { cv2[k] = v; ci2[k] = candi[j]; }
        }
    }
    __syncthreads();

    // ---- rank-based selection ----
    const int nc = (s_cnt2 < 512) ? s_cnt2 : 512;
    const bool valid = (tid < nc);
    float vk = -3.0e38f; int ik = 0x7FFFFFFF;
    if (valid) { vk = cv2[tid]; ik = ci2[tid]; }

    int rank = 0;
    for (int j = 0; j < nc; j++) {
        float vj = cv2[j]; int ij = ci2[j];
        if (valid && beats(vj, ij, vk, ik)) rank++;
    }

    int o0 = 0;
#pragma unroll
    for (int cc = 1; cc < N_CAMS; cc++) if (camMax[cc] > camMax[o0]) o0 = cc;
    int o1 = -1;
#pragma unroll
    for (int cc = 0; cc < N_CAMS; cc++) {
        if (cc == o0) continue;
        if (o1 < 0 || camMax[cc] > camMax[o1]) o1 = cc;
    }
    int o2 = -1;
#pragma unroll
    for (int cc = 0; cc < N_CAMS; cc++) {
        if (cc == o0 || cc == o1) continue;
        if (o2 < 0 || camMax[cc] > camMax[o2]) o2 = cc;
    }
    const float ev0 = camMax[o0], ev1 = camMax[o1], ev2 = camMax[o2];
    const int   ex0 = camIdx[o0], ex1 = camIdx[o1], ex2 = camIdx[o2];
    const float rp = s_rp;

    const int rankNp = rank - ((valid && beats(rp, p, vk, ik)) ? 1 : 0);
    if (valid && ik != p && rankNp == 0) s_top1 = vk;
    __syncthreads();

    const float pos = rp * INV_BETA;
    const float m1 = fmaxf(pos, s_top1 * INV_BETA);
    float e1 = 0.0f;
    if (valid && ik != p && rankNp < 50) e1 = expf(vk * INV_BETA - m1);
    if (tid == 0) e1 += expf(pos - m1);

    int rank3 = rank;
    if (valid) {
        rank3 -= (beats(ev0, ex0, vk, ik) ? 1 : 0);
        rank3 -= (beats(ev1, ex1, vk, ik) ? 1 : 0);
        rank3 -= (beats(ev2, ex2, vk, ik) ? 1 : 0);
    }
    const float m2 = ev0 * INV_BETA;
    float e2 = 0.0f;
    if (valid && ik != ex0 && ik != ex1 && ik != ex2 && rank3 < 30)
        e2 = expf(vk * INV_BETA - m2);
    if (tid == 0)
        e2 += 1.0f + expf(ev1 * INV_BETA - m2) + expf(ev2 * INV_BETA - m2);

#pragma unroll
    for (int o = 16; o > 0; o >>= 1) {
        e1 += __shfl_down_sync(0xffffffffu, e1, o);
        e2 += __shfl_down_sync(0xffffffffu, e2, o);
    }
    if (l == 0) { wmax[w] = e1; red[w] = e2; }
    __syncthreads();
    if (tid == 0) {
        float t1 = 0.0f, t2 = 0.0f;
        for (int i = 0; i < 16; i++) { t1 += wmax[i]; t2 += red[i]; }
        float* dst = g_loss + ((size_t)h * N_ROWS + n) * 3;
        dst[0] = s_ce;
        dst[1] = m1 + logf(t1) - pos;
        dst[2] = m2 + logf(t2) - (ev0 + ev1 + ev2) * INV_BETA * (1.0f / 3.0f);
    }
}

// ---------------- final deterministic weighted sum -------------------------------
__global__ void final_kernel(const int* __restrict__ cams, float* __restrict__ out)
{
    __shared__ double sd[N_ROWS];
    __shared__ int scams[N_ROWS];
    __shared__ int counts[N_CAMS];
    const int n = threadIdx.x;
    if (n < N_CAMS) counts[n] = 0;
    __syncthreads();
    scams[n] = cams[n];
    atomicAdd(&counts[scams[n]], 1);
    __syncthreads();
    const double w = 1.0 / (double)counts[scams[n]];
    const float* a = g_loss + (size_t)n * 3;
    const float* b = g_loss + (size_t)(N_ROWS + n) * 3;
    double t = 0.6 * ((double)a[0] + (double)b[0])
             + 0.7 * ((double)a[1] + (double)b[1])
             + 0.7 * ((double)a[2] + (double)b[2]);
    sd[n] = t * w;
    __syncthreads();
    for (int s = 256; s > 0; s >>= 1) {
        if (n < s) sd[n] += sd[n + s];
        __syncthreads();
    }
    if (n == 0) out[0] = (float)sd[0];
}

// ---------------- entry -----------------------------------------------------------
extern "C" void kernel_launch(void* const* d_in, const int* in_sizes, int n_in,
                              void* d_out, int out_size)
{
    const float* features = (const float*)d_in[0];
    const float* memory = (const float*)d_in[2];
    const int* cams  = (const int*)d_in[3];
    const int* proxy = (const int*)d_in[4];
    float* out = (float*)d_out;

    convA_k<<<(N_ROWS * D_FULL / 4) / 256, 256>>>(features);
    convB_k<<<((size_t)P_TOT * D_FULL / 4) / 256, 256>>>(memory);

    const int gsmem = 3 * (int)STG_B;   // 98304
    cudaFuncSetAttribute(gemm_mma, cudaFuncAttributeMaxDynamicSharedMemorySize, gsmem);
    dim3 ggrid(512, 2);
    gemm_mma<<<ggrid, 256, gsmem>>>();

    dim3 rgrid(N_ROWS, 2);
    reduce_kernel<<<rgrid, 512>>>(cams, proxy);

    final_kernel<<<1, N_ROWS>>>(cams, out);
}

// round 12
// speedup vs baseline: 1.0555x; 1.0555x over previous
#include <cuda_runtime.h>
#include <cuda.h>
#include <cuda_bf16.h>
#include <math.h>
#include <stdint.h>

// Problem constants
#define N_ROWS   512
#define N_CAMS   8
#define M_PER    2048
#define D_FULL   4096
#define K_HALF   2048
#define P_TOT    16384
#define TOPK     54
#define INV_BETA 20.0f

// ---------------- scratch (device globals) ------------------------------------
__device__ float g_sims[2ull * N_ROWS * P_TOT];                 // 64 MB
__device__ float g_loss[2 * N_ROWS * 3];
__device__ __nv_bfloat16 g_featB[(size_t)N_ROWS * D_FULL];      // 4 MB
__device__ __nv_bfloat16 g_memB[(size_t)P_TOT * D_FULL];        // 128 MB

// ---------------- helpers ------------------------------------------------------
__device__ __forceinline__ uint32_t smem_u32(const void* p) {
    uint32_t a;
    asm("{ .reg .u64 t; cvta.to.shared.u64 t, %1; cvt.u32.u64 %0, t; }"
        : "=r"(a) : "l"(p));
    return a;
}
__device__ __forceinline__ void mma16(float* d, const uint32_t* a,
                                      uint32_t b0, uint32_t b1) {
    asm volatile(
        "mma.sync.aligned.m16n8k16.row.col.f32.bf16.bf16.f32 "
        "{%0,%1,%2,%3}, {%4,%5,%6,%7}, {%8,%9}, {%0,%1,%2,%3};"
        : "+f"(d[0]), "+f"(d[1]), "+f"(d[2]), "+f"(d[3])
        : "r"(a[0]), "r"(a[1]), "r"(a[2]), "r"(a[3]), "r"(b0), "r"(b1));
}
__device__ __forceinline__ void ldsm4(uint32_t& r0, uint32_t& r1,
                                      uint32_t& r2, uint32_t& r3, uint32_t addr) {
    asm volatile("ldmatrix.sync.aligned.m8n8.x4.shared.b16 {%0,%1,%2,%3}, [%4];"
                 : "=r"(r0), "=r"(r1), "=r"(r2), "=r"(r3) : "r"(addr));
}
#define MBAR_INIT(a, c) \
    asm volatile("mbarrier.init.shared.b64 [%0], %1;" :: "r"(a), "r"(c) : "memory")
#define MBAR_EXPECT_TX(a, bytes) \
    asm volatile("mbarrier.arrive.expect_tx.shared.b64 _, [%0], %1;" \
                 :: "r"(a), "r"(bytes) : "memory")
__device__ __forceinline__ void mbar_wait(uint32_t a, uint32_t ph) {
    asm volatile(
        "{\n\t.reg .pred P;\n\t"
        "WL_%=:\n\t"
        "mbarrier.try_wait.parity.acquire.cta.shared::cta.b64 P, [%0], %1, 0x989680;\n\t"
        "@P bra.uni WD_%=;\n\t"
        "bra.uni WL_%=;\n\t"
        "WD_%=:\n\t}"
        :: "r"(a), "r"(ph) : "memory");
}
__device__ __forceinline__ void tma2d(uint32_t smem, const void* map,
                                      int x, int y, uint32_t mbar) {
    asm volatile(
        "cp.async.bulk.tensor.2d.shared::cta.global.tile.mbarrier::complete_tx::bytes "
        "[%0], [%1, {%2, %3}], [%4];"
        :: "r"(smem), "l"(map), "r"(x), "r"(y), "r"(mbar) : "memory");
}

// ---------------- fp32 -> bf16 conversion --------------------------------------
__global__ void convA_k(const float* __restrict__ f) {
    size_t i = (size_t)blockIdx.x * 256 + threadIdx.x;
    float4 v = ((const float4*)f)[i];
    __nv_bfloat162 p0 = __floats2bfloat162_rn(v.x, v.y);
    __nv_bfloat162 p1 = __floats2bfloat162_rn(v.z, v.w);
    uint2 o; o.x = *(uint32_t*)&p0; o.y = *(uint32_t*)&p1;
    ((uint2*)g_featB)[i] = o;
}
__global__ void convB_k(const float* __restrict__ m) {
    size_t i = (size_t)blockIdx.x * 256 + threadIdx.x;
    float4 v = ((const float4*)m)[i];
    __nv_bfloat162 p0 = __floats2bfloat162_rn(v.x, v.y);
    __nv_bfloat162 p1 = __floats2bfloat162_rn(v.z, v.w);
    uint2 o; o.x = *(uint32_t*)&p0; o.y = *(uint32_t*)&p1;
    ((uint2*)g_memB)[i] = o;
}

// ---------------- bf16 mma.sync GEMM: TMA loads, GBK=64, 3-stage, SW128 --------
#define GBK      64
#define NSTG     (K_HALF / GBK)     // 32
#define STG_B    32768u
#define B_OFF    16384u

__global__ void __launch_bounds__(256, 2)
gemm_tma(const __grid_constant__ CUtensorMap mapA,
         const __grid_constant__ CUtensorMap mapB) {
    extern __shared__ char sm[];
    const uint32_t sraw = smem_u32(sm);
    const uint32_t base = (sraw + 1023) & ~1023u;   // 1KB align (TMA + SW128)
    const uint32_t MBAR = base + 3 * STG_B;         // 3 x 8B mbarriers

    const int tid = threadIdx.x;
    const int bx = blockIdx.x;
    const int h  = blockIdx.y;
    const int ntile = bx >> 2;
    const int mtile = bx & 3;

    const int w  = tid >> 5;
    const int l  = tid & 31;
    const int wm = (w & 3) * 32;
    const int wn = (w >> 2) * 64;
    const int g  = l >> 2;
    const int tg = l & 3;

    // ldmatrix lane->addr (proven R8/R10); same SW128 layout TMA produces
    const int rowA  = wm + (l & 15);
    const int hiA   = (l >> 4) & 1;
    const uint32_t aRow = (uint32_t)rowA * 128;
    const int swA = rowA & 7;

    const int rowB  = wn + (l & 7) + ((l >> 4) & 1) * 8;
    const int hiB   = (l >> 3) & 1;
    const uint32_t bRow = B_OFF + (uint32_t)rowB * 128;
    const int swB = rowB & 7;

    if (tid == 0) {
        MBAR_INIT(MBAR + 0, 1);
        MBAR_INIT(MBAR + 8, 1);
        MBAR_INIT(MBAR + 16, 1);
    }
    __syncthreads();

    float acc[2][8][4];
#pragma unroll
    for (int mi = 0; mi < 2; mi++)
#pragma unroll
        for (int ni = 0; ni < 8; ni++)
#pragma unroll
            for (int c = 0; c < 4; c++) acc[mi][ni][c] = 0.0f;

    const int kg0 = h * K_HALF;
    if (tid == 0) {
#pragma unroll
        for (int st = 0; st < 2; st++) {
            const uint32_t buf = base + st * STG_B;
            MBAR_EXPECT_TX(MBAR + st * 8, (uint32_t)STG_B);
            tma2d(buf,         &mapA, kg0 + st * GBK, mtile * 128, MBAR + st * 8);
            tma2d(buf + B_OFF, &mapB, kg0 + st * GBK, ntile * 128, MBAR + st * 8);
        }
    }

    for (int st = 0; st < NSTG; st++) {
        const int b = st % 3;
        mbar_wait(MBAR + b * 8, (uint32_t)((st / 3) & 1));
        __syncthreads();   // all warps done with stage st-1 -> safe to refill (st+2)%3

        if (tid == 0 && st + 2 < NSTG) {
            const int b2 = (st + 2) % 3;
            const uint32_t buf = base + (uint32_t)b2 * STG_B;
            MBAR_EXPECT_TX(MBAR + b2 * 8, (uint32_t)STG_B);
            tma2d(buf,         &mapA, kg0 + (st + 2) * GBK, mtile * 128, MBAR + b2 * 8);
            tma2d(buf + B_OFF, &mapB, kg0 + (st + 2) * GBK, ntile * 128, MBAR + b2 * 8);
        }

        const uint32_t stg = base + (uint32_t)b * STG_B;
#pragma unroll
        for (int ks = 0; ks < 4; ks++) {
            const int ccA = ks * 2 + hiA;
            const int ccB = ks * 2 + hiB;
            uint32_t a[2][4];
            ldsm4(a[0][0], a[0][1], a[0][2], a[0][3],
                  stg + aRow + (uint32_t)((ccA ^ swA) << 4));
            ldsm4(a[1][0], a[1][1], a[1][2], a[1][3],
                  stg + aRow + 16u * 128u + (uint32_t)((ccA ^ swA) << 4));
            uint32_t bb[4][4];
#pragma unroll
            for (int np = 0; np < 4; np++)
                ldsm4(bb[np][0], bb[np][1], bb[np][2], bb[np][3],
                      stg + bRow + (uint32_t)np * 16u * 128u +
                      (uint32_t)((ccB ^ swB) << 4));
#pragma unroll
            for (int ni = 0; ni < 8; ni++) {
                const uint32_t b0 = bb[ni >> 1][(ni & 1) * 2];
                const uint32_t b1 = bb[ni >> 1][(ni & 1) * 2 + 1];
                mma16(acc[0][ni], a[0], b0, b1);
                mma16(acc[1][ni], a[1], b0, b1);
            }
        }
    }

    const int colbase = ntile * 128 + wn;
#pragma unroll
    for (int mi = 0; mi < 2; mi++) {
        const int row = mtile * 128 + wm + mi * 16 + g;
        float* d0 = g_sims + ((size_t)(h * N_ROWS + row)) * P_TOT + colbase + tg * 2;
        float* d1 = d0 + (size_t)8 * P_TOT;
#pragma unroll
        for (int ni = 0; ni < 8; ni++) {
            *(float2*)(d0 + ni * 8) = make_float2(acc[mi][ni][0], acc[mi][ni][1]);
            *(float2*)(d1 + ni * 8) = make_float2(acc[mi][ni][2], acc[mi][ni][3]);
        }
    }
}

// ---------------- per-row loss reduction (R10 proven 3-pass) ----------------------
__device__ __forceinline__ uint32_t fkey(float v) {
    uint32_t u = __float_as_uint(v);
    return u ^ (uint32_t)(((int32_t)u >> 31) | 0x80000000);
}
__device__ __forceinline__ bool beats(float va, int ia, float vb, int ib) {
    return (va > vb) || (va == vb && ia < ib);
}

__global__ void __launch_bounds__(512, 3)
reduce_kernel(const int* __restrict__ cams, const int* __restrict__ proxy)
{
    __shared__ int   hist1[256];
    __shared__ int   hist2[256];
    __shared__ float wmax[16];
    __shared__ int   widx[16];
    __shared__ float red[16];
    __shared__ float candv[512];
    __shared__ int   candi[512];
    __shared__ float camMax[N_CAMS];
    __shared__ int   camIdx[N_CAMS];
    __shared__ float s_ce, s_rp, s_top1;
    __shared__ int   s_b1, s_above, s_count;
    __shared__ uint32_t s_thr;

    const int n = blockIdx.x;
    const int h = blockIdx.y;
    const int tid = threadIdx.x;
    const int w = tid >> 5, l = tid & 31;

    if (tid < 256) { hist1[tid] = 0; hist2[tid] = 0; }
    if (tid == 0) s_count = 0;
    __syncthreads();

    const int c = cams[n];
    const int p = proxy[n];
    const float* rowg = g_sims + ((size_t)h * N_ROWS + n) * P_TOT;
    const float4* src4 = (const float4*)rowg;

    const int f4base = (w >> 1) * 512 + (w & 1) * 256;
    float bv = -3.0e38f; int bi = f4base * 4;
#pragma unroll
    for (int s = 0; s < 8; s++) {
        const int f4 = f4base + s * 32 + l;
        float4 v = __ldg(&src4[f4]);
        const int j = f4 * 4;
        if (v.x > bv) { bv = v.x; bi = j; }
        if (v.y > bv) { bv = v.y; bi = j + 1; }
        if (v.z > bv) { bv = v.z; bi = j + 2; }
        if (v.w > bv) { bv = v.w; bi = j + 3; }
        float comp[4] = {v.x, v.y, v.z, v.w};
#pragma unroll
        for (int q = 0; q < 4; q++) {
            uint32_t b = fkey(comp[q]) >> 24;
            unsigned m = __match_any_sync(0xffffffffu, b);
            if ((m & ((1u << l) - 1u)) == 0) atomicAdd(&hist1[b], __popc(m));
        }
    }
#pragma unroll
    for (int o = 16; o > 0; o >>= 1) {
        float ov = __shfl_down_sync(0xffffffffu, bv, o);
        int   oi = __shfl_down_sync(0xffffffffu, bi, o);
        if (ov > bv || (ov == bv && oi < bi)) { bv = ov; bi = oi; }
    }
    if (l == 0) { wmax[w] = bv; widx[w] = bi; }
    __syncthreads();

    if (tid < N_CAMS) {
        float a = wmax[2 * tid]; int ai = widx[2 * tid];
        float b2 = wmax[2 * tid + 1]; int bi2 = widx[2 * tid + 1];
        if (b2 > a || (b2 == a && bi2 < ai)) { a = b2; ai = bi2; }
        camMax[tid] = a; camIdx[tid] = ai;
    }
    if (tid == 32) {
        int cum = 0, b = 255;
        for (; b >= 0; b--) { cum += hist1[b]; if (cum >= TOPK) break; }
        s_b1 = b; s_above = cum - hist1[b];
    }
    __syncthreads();

    const uint32_t b1 = (uint32_t)s_b1;
    const float bm = camMax[c];
    float ssum = 0.0f;
#pragma unroll
    for (int s = 0; s < 8; s++) {
        const int f4 = tid + s * 512;
        float4 v = __ldg(&src4[f4]);
        float comp[4] = {v.x, v.y, v.z, v.w};
#pragma unroll
        for (int q = 0; q < 4; q++) {
            uint32_t k = fkey(comp[q]);
            if ((k >> 24) == b1) atomicAdd(&hist2[(k >> 16) & 0xFF], 1);
        }
        if (s == c) {
            ssum += expf((v.x - bm) * INV_BETA) + expf((v.y - bm) * INV_BETA)
                  + expf((v.z - bm) * INV_BETA) + expf((v.w - bm) * INV_BETA);
        }
    }
#pragma unroll
    for (int o = 16; o > 0; o >>= 1) ssum += __shfl_down_sync(0xffffffffu, ssum, o);
    if (l == 0) red[w] = ssum;
    __syncthreads();

    if (tid == 0) {
        int cum = s_above, b = 255;
        for (; b >= 0; b--) { cum += hist2[b]; if (cum >= TOPK) break; }
        s_thr = (b1 << 24) | ((uint32_t)b << 16);
        float tot = 0.0f;
        for (int i = 0; i < 16; i++) tot += red[i];
        const float rp = __ldg(&rowg[p]);
        s_rp = rp;
        s_ce = bm * INV_BETA + logf(tot) - rp * INV_BETA;
    }
    __syncthreads();

    const uint32_t thr = s_thr;
#pragma unroll
    for (int s = 0; s < 8; s++) {
        const int f4 = tid + s * 512;
        float4 v = __ldg(&src4[f4]);
        float comp[4] = {v.x, v.y, v.z, v.w};
#pragma unroll
        for (int q = 0; q < 4; q++) {
            if (fkey(comp[q]) >= thr) {
                int k = atomicAdd(&s_count, 1);
                if (k < 512) { candv[k] = comp[q]; candi[k] = f4 * 4 + q; }
            }
        }
    }
    __syncthreads();

    const int nc = (s_count < 512) ? s_count : 512;
    const bool valid = (tid < nc);
    float vk = -3.0e38f; int ik = 0x7FFFFFFF;
    if (valid) { vk = candv[tid]; ik = candi[tid]; }

    int rank = 0;
    for (int j = 0; j < nc; j++) {
        float vj = candv[j]; int ij = candi[j];
        if (valid && beats(vj, ij, vk, ik)) rank++;
    }

    int o0 = 0;
#pragma unroll
    for (int cc = 1; cc < N_CAMS; cc++) if (camMax[cc] > camMax[o0]) o0 = cc;
    int o1 = -1;
#pragma unroll
    for (int cc = 0; cc < N_CAMS; cc++) {
        if (cc == o0) continue;
        if (o1 < 0 || camMax[cc] > camMax[o1]) o1 = cc;
    }
    int o2 = -1;
#pragma unroll
    for (int cc = 0; cc < N_CAMS; cc++) {
        if (cc == o0 || cc == o1) continue;
        if (o2 < 0 || camMax[cc] > camMax[o2]) o2 = cc;
    }
    const float ev0 = camMax[o0], ev1 = camMax[o1], ev2 = camMax[o2];
    const int   ex0 = camIdx[o0], ex1 = camIdx[o1], ex2 = camIdx[o2];
    const float rp = s_rp;

    const int rankNp = rank - ((valid && beats(rp, p, vk, ik)) ? 1 : 0);
    if (valid && ik != p && rankNp == 0) s_top1 = vk;
    __syncthreads();

    const float pos = rp * INV_BETA;
    const float m1 = fmaxf(pos, s_top1 * INV_BETA);
    float e1 = 0.0f;
    if (valid && ik != p && rankNp < 50) e1 = expf(vk * INV_BETA - m1);
    if (tid == 0) e1 += expf(pos - m1);

    int rank3 = rank;
    if (valid) {
        rank3 -= (beats(ev0, ex0, vk, ik) ? 1 : 0);
        rank3 -= (beats(ev1, ex1, vk, ik) ? 1 : 0);
        rank3 -= (beats(ev2, ex2, vk, ik) ? 1 : 0);
    }
    const float m2 = ev0 * INV_BETA;
    float e2 = 0.0f;
    if (valid && ik != ex0 && ik != ex1 && ik != ex2 && rank3 < 30)
        e2 = expf(vk * INV_BETA - m2);
    if (tid == 0)
        e2 += 1.0f + expf(ev1 * INV_BETA - m2) + expf(ev2 * INV_BETA - m2);

#pragma unroll
    for (int o = 16; o > 0; o >>= 1) {
        e1 += __shfl_down_sync(0xffffffffu, e1, o);
        e2 += __shfl_down_sync(0xffffffffu, e2, o);
    }
    if (l == 0) { wmax[w] = e1; red[w] = e2; }
    __syncthreads();
    if (tid == 0) {
        float t1 = 0.0f, t2 = 0.0f;
        for (int i = 0; i < 16; i++) { t1 += wmax[i]; t2 += red[i]; }
        float* dst = g_loss + ((size_t)h * N_ROWS + n) * 3;
        dst[0] = s_ce;
        dst[1] = m1 + logf(t1) - pos;
        dst[2] = m2 + logf(t2) - (ev0 + ev1 + ev2) * INV_BETA * (1.0f / 3.0f);
    }
}

// ---------------- final deterministic weighted sum -------------------------------
__global__ void final_kernel(const int* __restrict__ cams, float* __restrict__ out)
{
    __shared__ double sd[N_ROWS];
    __shared__ int scams[N_ROWS];
    __shared__ int counts[N_CAMS];
    const int n = threadIdx.x;
    if (n < N_CAMS) counts[n] = 0;
    __syncthreads();
    scams[n] = cams[n];
    atomicAdd(&counts[scams[n]], 1);
    __syncthreads();
    const double w = 1.0 / (double)counts[scams[n]];
    const float* a = g_loss + (size_t)n * 3;
    const float* b = g_loss + (size_t)(N_ROWS + n) * 3;
    double t = 0.6 * ((double)a[0] + (double)b[0])
             + 0.7 * ((double)a[1] + (double)b[1])
             + 0.7 * ((double)a[2] + (double)b[2]);
    sd[n] = t * w;
    __syncthreads();
    for (int s = 256; s > 0; s >>= 1) {
        if (n < s) sd[n] += sd[n + s];
        __syncthreads();
    }
    if (n == 0) out[0] = (float)sd[0];
}

// ---------------- entry -----------------------------------------------------------
typedef CUresult (*TMEncodeFn)(
    CUtensorMap*, CUtensorMapDataType, cuuint32_t, void*,
    const cuuint64_t*, const cuuint64_t*, const cuuint32_t*, const cuuint32_t*,
    CUtensorMapInterleave, CUtensorMapSwizzle, CUtensorMapL2promotion,
    CUtensorMapFloatOOBfill);

extern "C" void kernel_launch(void* const* d_in, const int* in_sizes, int n_in,
                              void* d_out, int out_size)
{
    const float* features = (const float*)d_in[0];
    const float* memory = (const float*)d_in[2];
    const int* cams  = (const int*)d_in[3];
    const int* proxy = (const int*)d_in[4];
    float* out = (float*)d_out;

    convA_k<<<(N_ROWS * D_FULL / 4) / 256, 256>>>(features);
    convB_k<<<((size_t)P_TOT * D_FULL / 4) / 256, 256>>>(memory);

    // Build tensormaps (host-side; baked into the captured launch as params)
    void* fptr = nullptr;
    cudaDriverEntryPointQueryResult qr;
    cudaGetDriverEntryPoint("cuTensorMapEncodeTiled", &fptr, cudaEnableDefault, &qr);
    TMEncodeFn enc = (TMEncodeFn)fptr;

    void* dA = nullptr; cudaGetSymbolAddress(&dA, g_featB);
    void* dB = nullptr; cudaGetSymbolAddress(&dB, g_memB);

    CUtensorMap mapA, mapB;
    cuuint64_t dimsA[2] = {(cuuint64_t)D_FULL, (cuuint64_t)N_ROWS};
    cuuint64_t dimsB[2] = {(cuuint64_t)D_FULL, (cuuint64_t)P_TOT};
    cuuint64_t strides[1] = {(cuuint64_t)D_FULL * 2};
    cuuint32_t box[2] = {GBK, 128};
    cuuint32_t es[2] = {1, 1};
    enc(&mapA, CU_TENSOR_MAP_DATA_TYPE_BFLOAT16, 2, dA, dimsA, strides, box, es,
        CU_TENSOR_MAP_INTERLEAVE_NONE, CU_TENSOR_MAP_SWIZZLE_128B,
        CU_TENSOR_MAP_L2_PROMOTION_L2_128B, CU_TENSOR_MAP_FLOAT_OOB_FILL_NONE);
    enc(&mapB, CU_TENSOR_MAP_DATA_TYPE_BFLOAT16, 2, dB, dimsB, strides, box, es,
        CU_TENSOR_MAP_INTERLEAVE_NONE, CU_TENSOR_MAP_SWIZZLE_128B,
        CU_TENSOR_MAP_L2_PROMOTION_L2_128B, CU_TENSOR_MAP_FLOAT_OOB_FILL_NONE);

    const int gsmem = 1024 + 3 * (int)STG_B + 64;   // align slack + stages + mbars
    cudaFuncSetAttribute(gemm_tma, cudaFuncAttributeMaxDynamicSharedMemorySize, gsmem);
    dim3 ggrid(512, 2);
    gemm_tma<<<ggrid, 256, gsmem>>>(mapA, mapB);

    dim3 rgrid(N_ROWS, 2);
    reduce_kernel<<<rgrid, 512>>>(cams, proxy);

    final_kernel<<<1, N_ROWS>>>(cams, out);
}